// round 17
// baseline (speedup 1.0000x reference)
#include <cuda_runtime.h>
#include <math.h>

// ---------------- problem dims ----------------
#define EPSV 1e-5f
#define B 4
#define C 64           // input channels
#define H 128
#define W 128
#define HW (H*W)       // 16384
#define CMID 64        // compressed channels
#define O 100          // encoder output channels (25 kernels * 4 quadrants)
#define OPAD 112       // padded O (28 groups of 4)
#define NTAP 9

// ---------------- device scratch (no allocation allowed) ----------------
__device__ float g_M[B*CMID*HW];              // compressed feature map
__device__ float g_E[B*O*HW];                 // encoder output (pre-softmax)
__device__ float g_wdup[NTAP*CMID*OPAD*2];    // BN-folded enc weights, each value DUPLICATED: [tap][cm][o][2]
__device__ float g_benc[OPAD];                // folded bias+BN

// ---------------- packed fp32x2 FMA (Blackwell, PTX-only) ----------------
__device__ __forceinline__ void ffma2(float2& d, float2 a, float2 b) {
    asm("fma.rn.f32x2 %0, %1, %2, %0;"
        : "+l"(reinterpret_cast<unsigned long long&>(d))
        : "l"(reinterpret_cast<unsigned long long&>(a)),
          "l"(reinterpret_cast<unsigned long long&>(b)));
}

// =====================================================================
// K0: prep — fold enc BN into weights, duplicate each value (f32x2-ready),
// pad O 100->112, layout [tap][cm][o][2]
// =====================================================================
__global__ void k_prep(const float* __restrict__ enc_w, const float* __restrict__ enc_b,
                       const float* __restrict__ eg, const float* __restrict__ ebt,
                       const float* __restrict__ em, const float* __restrict__ ev) {
    int gid = blockIdx.x * blockDim.x + threadIdx.x;
    if (gid < NTAP*CMID*OPAD) {
        int o   = gid % OPAD;
        int cm  = (gid / OPAD) & 63;
        int tap = gid / (OPAD*CMID);
        float v = 0.f;
        if (o < O) {
            float inv = eg[o] * rsqrtf(ev[o] + EPSV);
            v = enc_w[o*576 + cm*9 + tap] * inv;   // enc_w is [O][CMID][3][3]
        }
        g_wdup[gid*2]   = v;
        g_wdup[gid*2+1] = v;
    }
    if (gid < OPAD) {
        float v = 0.f;
        if (gid < O) {
            float inv = eg[gid] * rsqrtf(ev[gid] + EPSV);
            v = enc_b[gid]*inv + ebt[gid] - em[gid]*inv;
        }
        g_benc[gid] = v;
    }
}

// =====================================================================
// K1: compress — 1x1 conv (64x64 GEMM per pixel) + BN + ReLU -> g_M
// =====================================================================
__global__ __launch_bounds__(256) void k_compress(
        const float* __restrict__ X, const float* __restrict__ cw,
        const float* __restrict__ cg, const float* __restrict__ cb,
        const float* __restrict__ cmu, const float* __restrict__ cv) {
    __shared__ float sw1[C*CMID];   // [c][cm] transposed + BN folded
    __shared__ float sb1[CMID];
    int tid = threadIdx.x;
    for (int i = tid; i < C*CMID; i += 256) {
        int cmi = i & 63, c = i >> 6;
        float inv = cg[cmi] * rsqrtf(cv[cmi] + EPSV);
        sw1[i] = cw[cmi*C + c] * inv;
    }
    if (tid < CMID) {
        float inv = cg[tid] * rsqrtf(cv[tid] + EPSV);
        sb1[tid] = cb[tid] - cmu[tid]*inv;
    }
    __syncthreads();

    int gid = blockIdx.x * 256 + tid;
    int b = gid >> 14, s = gid & (HW-1);
    const float* xp = X + (size_t)b*C*HW + s;

    float2 acc[CMID/2];
#pragma unroll
    for (int j = 0; j < CMID/2; j++) acc[j] = make_float2(0.f, 0.f);

    for (int c = 0; c < C; c++) {
        float xv = xp[c*HW];
        float2 x2 = make_float2(xv, xv);
        const float2* wr = reinterpret_cast<const float2*>(&sw1[c*CMID]);
#pragma unroll
        for (int j = 0; j < CMID/2; j++) ffma2(acc[j], wr[j], x2);
    }

    float* mp = g_M + (size_t)b*CMID*HW + s;
#pragma unroll
    for (int j = 0; j < CMID/2; j++) {
        mp[(2*j  )*HW] = fmaxf(acc[j].x + sb1[2*j  ], 0.f);
        mp[(2*j+1)*HW] = fmaxf(acc[j].y + sb1[2*j+1], 0.f);
    }
}

// =====================================================================
// K2: encode v3 — 3x3 conv as GEMM; f32x2 pairs PIXEL COLUMNS (not o).
// Weights arrive pre-duplicated via LDG.64 (zero MOV duplication).
// m-operand is a contiguous pixel pair: LDS.64 for dj even, 2x LDS.32
// for dj==1 (odd smem offset). Thread = (o-quad to=0..27, col-pair tp=0..7),
// covers 4 o x 8 rows x 2 cols. OPAD=112 trims padding waste.
// =====================================================================
#define TH 8
#define TW 16
#define ETHR 224
__global__ __launch_bounds__(ETHR, 2) void k_encode() {
    __shared__ __align__(16) float sM[CMID*180];   // 64 ch x (8+2) x (16+2) halo = 46.08 KB

    int tid = threadIdx.x;
    int to = tid >> 3;          // 0..27 -> o = to*4 + u
    int tp = tid & 7;           // col pair: cols 2tp, 2tp+1
    int b   = blockIdx.z;
    int yl0 = blockIdx.y * TH;
    int xl0 = blockIdx.x * TW;

    // load halo tile (zero-pad at borders)
    for (int i = tid; i < CMID*180; i += ETHR) {
        int cm = i / 180;
        int rem = i - cm*180;
        int rr = rem / 18, cc = rem - rr*18;
        int gy = yl0 + rr - 1, gx = xl0 + cc - 1;
        float v = 0.f;
        if ((unsigned)gy < H && (unsigned)gx < W)
            v = g_M[((size_t)(b*CMID + cm) << 14) + gy*W + gx];
        sM[i] = v;
    }
    __syncthreads();

    float2 acc[4][8];   // [o in quad][row], lanes = (col 2tp, col 2tp+1)
#pragma unroll
    for (int u = 0; u < 4; u++)
#pragma unroll
        for (int r = 0; r < 8; r++) acc[u][r] = make_float2(0.f, 0.f);

    for (int tap = 0; tap < 9; tap++) {
        int di = tap / 3, dj = tap - di*3;
        int mbase = di*18 + dj + 2*tp;
        // wdup row for this tap: [cm][OPAD*2]; thread's 4 dup-pairs at float2 idx kk*OPAD + to*4 + u
        const float2* wb = reinterpret_cast<const float2*>(g_wdup) + (size_t)tap*(CMID*OPAD) + to*4;

        if (dj == 1) {
            // odd smem offset: scalar assembly of the pixel pair
#pragma unroll 2
            for (int kk = 0; kk < CMID; kk++) {
                float2 w2[4];
#pragma unroll
                for (int u = 0; u < 4; u++) w2[u] = __ldg(&wb[kk*OPAD + u]);
                const float* mp = &sM[kk*180 + mbase];
                float2 m2[8];
#pragma unroll
                for (int r = 0; r < 8; r++) {
                    m2[r].x = mp[r*18];
                    m2[r].y = mp[r*18 + 1];
                }
#pragma unroll
                for (int u = 0; u < 4; u++)
#pragma unroll
                    for (int r = 0; r < 8; r++) ffma2(acc[u][r], m2[r], w2[u]);
            }
        } else {
            // even smem offset: natural LDS.64 pixel pairs
#pragma unroll 2
            for (int kk = 0; kk < CMID; kk++) {
                float2 w2[4];
#pragma unroll
                for (int u = 0; u < 4; u++) w2[u] = __ldg(&wb[kk*OPAD + u]);
                const float2* mp = reinterpret_cast<const float2*>(&sM[kk*180 + mbase]);
                float2 m2[8];
#pragma unroll
                for (int r = 0; r < 8; r++) m2[r] = mp[r*9];
#pragma unroll
                for (int u = 0; u < 4; u++)
#pragma unroll
                    for (int r = 0; r < 8; r++) ffma2(acc[u][r], m2[r], w2[u]);
            }
        }
    }

    // epilogue: add folded bias, STG.64 per (o, row) (skip padded o >= 100)
#pragma unroll
    for (int u = 0; u < 4; u++) {
        int o = to*4 + u;
        if (o < O) {
            float bv = g_benc[o];
#pragma unroll
            for (int r = 0; r < 8; r++) {
                float* ep = g_E + ((size_t)(b*O + o) << 14) + (yl0 + r)*W + xl0 + 2*tp;
                *reinterpret_cast<float2*>(ep) =
                    make_float2(acc[u][r].x + bv, acc[u][r].y + bv);
            }
        }
    }
}

// =====================================================================
// K3: pixel-shuffle + softmax + CARAFE gather (fused), v3 — unchanged
// =====================================================================
__global__ __launch_bounds__(256) void k_carafe(const float* __restrict__ X,
                                                float* __restrict__ out) {
    __shared__ float sw2[O*64];      // weights transposed [o][pix]   (25.6 KB)
    __shared__ __align__(16) float sx[16*320];  // 16 ch-pairs x 8x20 halo, pair-interleaved

    int tid = threadIdx.x;
    int b   = blockIdx.z;
    int yl0 = blockIdx.y * 4;
    int xl0 = blockIdx.x * 16;

    // ---- Phase A: stage E transposed (coalesced both sides), softmax ----
    for (int j = tid; j < 64*O; j += 256) {
        int o = j >> 6, pix = j & 63;
        int row = pix >> 4, col = pix & 15;
        sw2[o*64 + pix] = g_E[((size_t)(b*O + o) << 14) + (yl0 + row)*W + xl0 + col];
    }
    __syncthreads();
    {
        int spix = tid >> 2, q = tid & 3;
        float* wp = &sw2[q*64 + spix];
        float e[25];
        float mx = -1e30f;
#pragma unroll
        for (int k = 0; k < 25; k++) { e[k] = wp[k*256]; mx = fmaxf(mx, e[k]); }
        float s = 0.f;
#pragma unroll
        for (int k = 0; k < 25; k++) { e[k] = expf(e[k] - mx); s += e[k]; }
        float inv = 1.f / s;
#pragma unroll
        for (int k = 0; k < 25; k++) wp[k*256] = e[k]*inv;
    }

    int pix = tid & 63;
    int grp = tid >> 6;             // channel group 0..3 (4 pairs each per half)
    int rloc = pix >> 4, col = pix & 15;

    const float* outb = out + (size_t)b*C*(4*HW);
    int oy = 2*(yl0 + rloc);
    int ox = 2*(xl0 + col);

    for (int half = 0; half < 2; half++) {
        __syncthreads();
        for (int i = tid; i < 16*160; i += 256) {
            int cp = i / 160;
            int sp = i - cp*160;
            int rr = sp / 20, cc = sp - rr*20;
            int gy = yl0 + rr - 2, gx = xl0 + cc - 2;
            float2 v = make_float2(0.f, 0.f);
            if ((unsigned)gy < H && (unsigned)gx < W) {
                const float* xp = X + ((size_t)(b*C + half*32 + 2*cp) << 14) + gy*W + gx;
                v.x = xp[0];
                v.y = xp[HW];
            }
            *reinterpret_cast<float2*>(&sx[cp*320 + sp*2]) = v;
        }
        __syncthreads();

        float2 acc[4][4];   // [pair][quadrant]
#pragma unroll
        for (int p = 0; p < 4; p++)
#pragma unroll
            for (int q = 0; q < 4; q++) acc[p][q] = make_float2(0.f, 0.f);

#pragma unroll
        for (int i5 = 0; i5 < 5; i5++)
#pragma unroll
            for (int j5 = 0; j5 < 5; j5++) {
                int k = i5*5 + j5;
                float2 wq[4];
#pragma unroll
                for (int q = 0; q < 4; q++) {
                    float wv = sw2[(4*k + q)*64 + pix];
                    wq[q] = make_float2(wv, wv);
                }
                int xoff = ((rloc + i5)*20 + col + j5)*2;
#pragma unroll
                for (int p = 0; p < 4; p++) {
                    float2 x2 = *reinterpret_cast<const float2*>(
                        &sx[(grp*4 + p)*320 + xoff]);
#pragma unroll
                    for (int q = 0; q < 4; q++) ffma2(acc[p][q], x2, wq[q]);
                }
            }

#pragma unroll
        for (int p = 0; p < 4; p++) {
            int c0 = (half*16 + grp*4 + p)*2;
#pragma unroll
            for (int dy = 0; dy < 2; dy++) {
                float* op = (float*)outb + ((size_t)c0*(2*H) + oy + dy)*(2*W) + ox;
                *reinterpret_cast<float2*>(op) =
                    make_float2(acc[p][2*dy].x, acc[p][2*dy+1].x);
                *reinterpret_cast<float2*>(op + 4*HW) =
                    make_float2(acc[p][2*dy].y, acc[p][2*dy+1].y);
            }
        }
    }
}

// =====================================================================
// launch
// =====================================================================
extern "C" void kernel_launch(void* const* d_in, const int* in_sizes, int n_in,
                              void* d_out, int out_size) {
    const float* X      = (const float*)d_in[0];
    const float* comp_w = (const float*)d_in[1];
    const float* comp_g = (const float*)d_in[2];
    const float* comp_b = (const float*)d_in[3];
    const float* comp_m = (const float*)d_in[4];
    const float* comp_v = (const float*)d_in[5];
    const float* enc_w  = (const float*)d_in[6];
    const float* enc_b  = (const float*)d_in[7];
    const float* enc_g  = (const float*)d_in[8];
    const float* enc_bt = (const float*)d_in[9];
    const float* enc_m  = (const float*)d_in[10];
    const float* enc_v  = (const float*)d_in[11];
    float* out = (float*)d_out;

    k_prep<<<(NTAP*CMID*OPAD + 255)/256, 256>>>(enc_w, enc_b, enc_g, enc_bt, enc_m, enc_v);
    k_compress<<<(B*HW)/256, 256>>>(X, comp_w, comp_g, comp_b, comp_m, comp_v);

    dim3 g2(W/TW, H/TH, B);   // (8, 16, 4)
    k_encode<<<g2, ETHR>>>();

    dim3 g3(W/16, H/4, B);    // (8, 32, 4)
    k_carafe<<<g3, 256>>>(X, out);
}